// round 2
// baseline (speedup 1.0000x reference)
#include <cuda_runtime.h>

// Problem constants (fixed by reference): HN=10, ND=40, HF=8, STRIDE=3, ESTRIDE=3
// A_ENC: agg[j] = sum x[4j-3 .. 4j+2 mod 40]
// A_PRED: agg2[d] = z1[d] + w*(z1[d-1] + z1[d+1]), w = exp(-1/9)
// A_DEC per grid i (m = i%4):
//   m==0: s[i/4]; m==1: s[(i-1)/4]+s[(i+3)/4 %10]; m==2: s[(i-2)/4]+s[(i+2)/4 %10]; m==3: s[(i+1)/4 %10]

typedef unsigned long long u64;

__device__ __forceinline__ u64 pk2(float a, float b) {
    u64 r; asm("mov.b64 %0, {%1, %2};" : "=l"(r) : "f"(a), "f"(b)); return r;
}
__device__ __forceinline__ void upk2(u64 v, float& a, float& b) {
    asm("mov.b64 {%0, %1}, %2;" : "=f"(a), "=f"(b) : "l"(v));
}
__device__ __forceinline__ u64 ffma2(u64 a, u64 b, u64 c) {
    u64 d; asm("fma.rn.f32x2 %0, %1, %2, %3;" : "=l"(d) : "l"(a), "l"(b), "l"(c)); return d;
}

// Pre-packed weights (written by prep_kernel each launch; deterministic)
__device__ u64 g_encW[8][4];   // [g][f2] = (enc_root_w[2f2][g], enc_root_w[2f2+1][g])
__device__ u64 g_encRW[4];     // (enc_rel_w[2f2], enc_rel_w[2f2+1])
__device__ u64 g_encB[4];      // enc_rel_b pairs
__device__ u64 g_W1[8][4];     // (pred_rel_w + pred_root_w) pairs, [g][f2]
__device__ u64 g_W2[8][4];     // (exp(-1/9) * pred_rel_w) pairs, [g][f2]
__device__ u64 g_predB[4];     // pred_rel_b pairs
__device__ float g_drw[8];     // dec_rel_w
__device__ float g_dec2[2];    // dec_rel_b, dec_root_w

__global__ void prep_kernel(const float* __restrict__ erw, const float* __restrict__ erb,
                            const float* __restrict__ erow,
                            const float* __restrict__ prw, const float* __restrict__ prb,
                            const float* __restrict__ prow,
                            const float* __restrict__ drw, const float* __restrict__ drb,
                            const float* __restrict__ droot) {
    const int t = threadIdx.x;
    const float wE = expf(-1.0f / 9.0f);
    if (t < 32) {
        const int g = t & 7, f2 = t >> 3;   // f2 in 0..3
        const int i0 = (2 * f2) * 8 + g;
        const int i1 = (2 * f2 + 1) * 8 + g;
        g_encW[g][f2] = pk2(erow[i0], erow[i1]);
        g_W1[g][f2]   = pk2(prw[i0] + prow[i0], prw[i1] + prow[i1]);
        g_W2[g][f2]   = pk2(wE * prw[i0], wE * prw[i1]);
    }
    if (t < 4) {
        g_encRW[t] = pk2(erw[2 * t], erw[2 * t + 1]);
        g_encB[t]  = pk2(erb[2 * t], erb[2 * t + 1]);
        g_predB[t] = pk2(prb[2 * t], prb[2 * t + 1]);
    }
    if (t < 8) g_drw[t] = drw[t];
    if (t == 0) { g_dec2[0] = drb[0]; g_dec2[1] = droot[0]; }
}

// Shared layout (dynamic): xs float4[128*11] | zs float4[128*21] | ss float[128*10]
// 22528 + 43008 + 5120 = 70656 bytes
#define SMEM_BYTES 70656

__global__ __launch_bounds__(128, 2)
void gnn_kernel(const float* __restrict__ x, const float* __restrict__ z,
                const float* __restrict__ y, float* __restrict__ out) {
    extern __shared__ char smem[];
    float4* xs = (float4*)smem;            // [128][11] (10 used) — lane stride 11 (3 mod 8): conflict-free
    float4* zs = xs + 128 * 11;            // [128][21] (20 used) — lane stride 21 (5 mod 8): conflict-free
    float*  ss = (float*)(zs + 128 * 21);  // [128][10]

    const int t = threadIdx.x;
    const long long blk = blockIdx.x;

    // ---- Stage in x and z with coalesced float4 loads ----
    const float4* xg = (const float4*)x + blk * 1280;   // 128 rows * 10 float4
    const float4* zg = (const float4*)z + blk * 2560;   // 128 rows * 20 float4
#pragma unroll
    for (int k = 0; k < 10; k++) {
        const int i4 = t + k * 128;
        xs[(i4 / 10) * 11 + (i4 % 10)] = xg[i4];
    }
#pragma unroll
    for (int k = 0; k < 20; k++) {
        const int i4 = t + k * 128;
        zs[(i4 / 20) * 21 + (i4 % 20)] = zg[i4];
    }
    __syncthreads();

    // ---- Per-element compute: thread t handles element blk*128 + t ----
    float xv[40];
#pragma unroll
    for (int c = 0; c < 10; c++) {
        const float4 v = xs[t * 11 + c];
        xv[4 * c + 0] = v.x; xv[4 * c + 1] = v.y; xv[4 * c + 2] = v.z; xv[4 * c + 3] = v.w;
    }

    // Encoder aggregation: agg[j] = sum of 6 grid values around 4j
    float agg[10];
#pragma unroll
    for (int j = 0; j < 10; j++) {
        float s0 = 0.0f;
#pragma unroll
        for (int k = 0; k < 6; k++) s0 += xv[(4 * j - 3 + k + 40) % 40];
        agg[j] = s0;
    }

    // Stage A: z1[j][f] = relu(agg[j]*erw[f] + erb[f] + sum_g z[j][g]*erow[f][g])
    float z1[10][8];
#pragma unroll
    for (int j = 0; j < 10; j++) {
        const float4 a = zs[t * 21 + 2 * j];
        const float4 b = zs[t * 21 + 2 * j + 1];
        const float zr[8] = {a.x, a.y, a.z, a.w, b.x, b.y, b.z, b.w};
        u64 acc[4];
        const u64 ab = pk2(agg[j], agg[j]);
#pragma unroll
        for (int f2 = 0; f2 < 4; f2++) acc[f2] = ffma2(ab, g_encRW[f2], g_encB[f2]);
#pragma unroll
        for (int g = 0; g < 8; g++) {
            const u64 zb = pk2(zr[g], zr[g]);
#pragma unroll
            for (int f2 = 0; f2 < 4; f2++) acc[f2] = ffma2(zb, g_encW[g][f2], acc[f2]);
        }
#pragma unroll
        for (int f2 = 0; f2 < 4; f2++) {
            float lo, hi; upk2(acc[f2], lo, hi);
            z1[j][2 * f2]     = fmaxf(lo, 0.0f);
            z1[j][2 * f2 + 1] = fmaxf(hi, 0.0f);
        }
    }

    // Stage B: z2[d] = relu(z1[d]@W1^T + (z1[d-1]+z1[d+1])@W2^T + prb); s[d] = z2[d]·drw
#pragma unroll
    for (int d = 0; d < 10; d++) {
        const int dm = (d + 9) % 10, dp = (d + 1) % 10;
        u64 acc[4];
#pragma unroll
        for (int f2 = 0; f2 < 4; f2++) acc[f2] = g_predB[f2];
#pragma unroll
        for (int g = 0; g < 8; g++) {
            const u64 zb = pk2(z1[d][g], z1[d][g]);
            const float u = z1[dm][g] + z1[dp][g];
            const u64 ub = pk2(u, u);
#pragma unroll
            for (int f2 = 0; f2 < 4; f2++) acc[f2] = ffma2(zb, g_W1[g][f2], acc[f2]);
#pragma unroll
            for (int f2 = 0; f2 < 4; f2++) acc[f2] = ffma2(ub, g_W2[g][f2], acc[f2]);
        }
        float sd = 0.0f;
#pragma unroll
        for (int f2 = 0; f2 < 4; f2++) {
            float lo, hi; upk2(acc[f2], lo, hi);
            sd += fmaxf(lo, 0.0f) * g_drw[2 * f2] + fmaxf(hi, 0.0f) * g_drw[2 * f2 + 1];
        }
        ss[t * 10 + d] = sd;
    }
    __syncthreads();

    // ---- Decoder / output pass: fully coalesced float4 y-load + out-store ----
    const float drb   = g_dec2[0];
    const float droot = g_dec2[1];
    const float4* yg = (const float4*)y + blk * 1280;
    float4* og = (float4*)out + blk * 1280;
#pragma unroll
    for (int p = 0; p < 10; p++) {
        const int n4 = t + p * 128;
        const int bl = n4 / 10, c = n4 % 10;
        const float sa = ss[bl * 10 + c];
        const float sb = ss[bl * 10 + (c == 9 ? 0 : c + 1)];
        const float4 yv = yg[n4];
        float4 o;
        o.x = sa + drb + yv.x * droot;          // i = 4c   (m=0)
        o.y = sa + sb + drb + yv.y * droot;     // i = 4c+1 (m=1)
        o.z = sa + sb + drb + yv.z * droot;     // i = 4c+2 (m=2)
        o.w = sb + drb + yv.w * droot;          // i = 4c+3 (m=3)
        og[n4] = o;
    }
}

extern "C" void kernel_launch(void* const* d_in, const int* in_sizes, int n_in,
                              void* d_out, int out_size) {
    const float* x     = (const float*)d_in[0];
    const float* z     = (const float*)d_in[1];
    const float* y     = (const float*)d_in[2];
    const float* erw   = (const float*)d_in[3];
    const float* erb   = (const float*)d_in[4];
    const float* erow  = (const float*)d_in[5];
    const float* prw   = (const float*)d_in[6];
    const float* prb   = (const float*)d_in[7];
    const float* prow  = (const float*)d_in[8];
    const float* drw   = (const float*)d_in[9];
    const float* drb   = (const float*)d_in[10];
    const float* droot = (const float*)d_in[11];

    const int B = in_sizes[0] / 40;       // 524288
    const int blocks = B / 128;           // 4096

    cudaFuncSetAttribute(gnn_kernel, cudaFuncAttributeMaxDynamicSharedMemorySize, SMEM_BYTES);
    prep_kernel<<<1, 32>>>(erw, erb, erow, prw, prb, prow, drw, drb, droot);
    gnn_kernel<<<blocks, 128, SMEM_BYTES>>>(x, z, y, (float*)d_out);
}